// round 13
// baseline (speedup 1.0000x reference)
#include <cuda_runtime.h>

#define NB 1024
#define NR 512
#define ND 128
#define NO 64
#define BETA 6.5f
#define LAM_A 0.0033f
#define LAM_W 0.003f

// scratch (allocation-free rule: __device__ globals)
__device__ float g_cT[ND * NR];         // c transposed: [d][r]
__device__ float g_coef[NB * NR];
__device__ float g_P[NB];
__device__ float g_Qp[4 * NB * ND];     // k4 split-R partials
__device__ float g_Sp[4 * NB * ND];

// ---------------------------------------------------------------------------
// K0T: transpose c (R x D) -> cT (D x R).  32x32 tiles, grid (16, 4).
// ---------------------------------------------------------------------------
__global__ __launch_bounds__(256) void k0_transpose(const float* __restrict__ c)
{
    __shared__ float t[32][33];
    int rt = blockIdx.x * 32;   // r tile
    int dt = blockIdx.y * 32;   // d tile
    int x = threadIdx.x & 31, y = threadIdx.x >> 5;   // 32 x 8
#pragma unroll
    for (int i = 0; i < 32; i += 8)
        t[y + i][x] = c[(rt + y + i) * ND + dt + x];
    __syncthreads();
#pragma unroll
    for (int i = 0; i < 32; i += 8)
        g_cT[(dt + y + i) * NR + rt + x] = t[x][y + i];
}

// ---------------------------------------------------------------------------
// K23: one block per b. assoc row register-resident (DRAM read exactly once).
// Fused q-compute: q[b,r] = t0 + sum_d (u[d] + a[d]*c[r,d])*c[r,d], hidden
// under the assoc DRAM load latency (c read d-major from L2 via g_cT).
// Then s,h -> x -> gx -> coef + new_assoc (registers) -> P.
// ---------------------------------------------------------------------------
__global__ __launch_bounds__(512) void k23(
    const float* __restrict__ assoc, const float* __restrict__ label,
    const float* __restrict__ z, const float* __restrict__ attn,
    float* __restrict__ out_x, float* __restrict__ out_assoc)
{
    __shared__ __align__(16) float uu[ND];   // -2*a*z
    __shared__ __align__(16) float vv[ND];   // a
    __shared__ float ss[NR];
    __shared__ float hh[NR];
    __shared__ __align__(16) float red[32][NO];
    __shared__ __align__(16) float gx[NO];
    __shared__ __align__(16) float coef[NR];
    __shared__ float t0sh;

    int b = blockIdx.x;
    int tid = threadIdx.x;
    int o4 = tid & 15, rg = tid >> 4;

    const float4* ab4 = (const float4*)(assoc + (size_t)b * NR * NO);

    // Issue all 16 payload loads up-front (independent -> MLP 16/thread).
    float4 av[16];
#pragma unroll
    for (int i = 0; i < 16; i++)
        av[i] = __ldg(ab4 + (rg + 32 * i) * 16 + o4);

    // u,v into smem (first 128 threads)
    if (tid < ND) {
        float a  = attn[b * ND + tid];
        float zz = z[b * ND + tid];
        uu[tid] = -2.f * a * zz;
        vv[tid] = a;
    }
    // t0[b] = sum_d attn*z^2  (warp 0)
    if (tid < 32) {
        float4 zz = *(const float4*)&z[b * ND + tid * 4];
        float4 aa = *(const float4*)&attn[b * ND + tid * 4];
        float t = aa.x * zz.x * zz.x + aa.y * zz.y * zz.y
                + aa.z * zz.z * zz.z + aa.w * zz.w * zz.w;
#pragma unroll
        for (int off = 16; off; off >>= 1)
            t += __shfl_xor_sync(0xffffffffu, t, off);
        if (tid == 0) t0sh = t;
    }
    __syncthreads();

    // Fused q-compute for r = tid (c read d-major -> fully coalesced, L2-hot).
    // Hidden under the in-flight assoc DRAM loads.
    {
        float acc = 0.f;
        const float* cT = g_cT + tid;
#pragma unroll 8
        for (int d = 0; d < ND; d += 4) {
            float4 u4 = *(const float4*)&uu[d];
            float4 v4 = *(const float4*)&vv[d];
            float c0 = __ldg(cT + (d + 0) * NR);
            float c1 = __ldg(cT + (d + 1) * NR);
            float c2 = __ldg(cT + (d + 2) * NR);
            float c3 = __ldg(cT + (d + 3) * NR);
            acc = fmaf(fmaf(v4.x, c0, u4.x), c0, acc);
            acc = fmaf(fmaf(v4.y, c1, u4.y), c1, acc);
            acc = fmaf(fmaf(v4.z, c2, u4.z), c2, acc);
            acc = fmaf(fmaf(v4.w, c3, u4.w), c3, acc);
        }
        float q = fmaxf(acc + t0sh, 1e-12f);
        float dd = sqrtf(q);
        float s = __expf(-BETA * dd);
        ss[tid] = s;
        hh[tid] = -0.5f * BETA * s / dd;
    }
    __syncthreads();

    // Phase 1: x reduction from registers
    {
        float4 acc = make_float4(0.f, 0.f, 0.f, 0.f);
#pragma unroll
        for (int i = 0; i < 16; i++) {
            float s = ss[rg + 32 * i];
            acc.x = fmaf(s, av[i].x, acc.x);
            acc.y = fmaf(s, av[i].y, acc.y);
            acc.z = fmaf(s, av[i].z, acc.z);
            acc.w = fmaf(s, av[i].w, acc.w);
        }
        *(float4*)&red[rg][o4 * 4] = acc;
    }
    __syncthreads();
    if (tid < NO) {
        float x = 0.f;
#pragma unroll
        for (int g2 = 0; g2 < 32; g2++) x += red[g2][tid];
        float l = label[b * NO + tid];
        float tmin = fminf(-1.f, x);
        float teacher = tmin - l * tmin + l * fmaxf(1.f, x);
        out_x[b * NO + tid] = 2.f * x;                 // PHI = 2
        gx[tid] = 0.03125f * (x - teacher);            // (2/O)*(x - teacher)
    }
    __syncthreads();

    // Phase A: coef + new_assoc from registers (zero re-read)
    {
        float4 g4 = *(const float4*)&gx[o4 * 4];
        float4* ob4 = (float4*)(out_assoc + (size_t)b * NR * NO);
#pragma unroll
        for (int i = 0; i < 16; i++) {
            int r = rg + 32 * i;
            float p = av[i].x * g4.x + av[i].y * g4.y
                    + av[i].z * g4.z + av[i].w * g4.w;
            float f = LAM_W * ss[r];
            float4 o;
            o.x = fmaf(-f, g4.x, av[i].x);
            o.y = fmaf(-f, g4.y, av[i].y);
            o.z = fmaf(-f, g4.z, av[i].z);
            o.w = fmaf(-f, g4.w, av[i].w);
            ob4[r * 16 + o4] = o;
            p += __shfl_xor_sync(0xffffffffu, p, 1);
            p += __shfl_xor_sync(0xffffffffu, p, 2);
            p += __shfl_xor_sync(0xffffffffu, p, 4);
            p += __shfl_xor_sync(0xffffffffu, p, 8);
            if (o4 == 0) coef[r] = hh[r] * p;
        }
    }
    __syncthreads();

    if (tid < NR / 4)
        ((float4*)&g_coef[b * NR])[tid] = ((const float4*)coef)[tid];
    if (tid < 32) {
        float p = 0.f;
#pragma unroll
        for (int i = 0; i < 16; i++) p += coef[tid + 32 * i];
#pragma unroll
        for (int off = 16; off; off >>= 1)
            p += __shfl_xor_sync(0xffffffffu, p, off);
        if (tid == 0) g_P[b] = p;
    }
}

// ---------------------------------------------------------------------------
// K4: dual GEMM partials  Q = coef @ C, S = coef @ C^2
// M=1024(b), N=128(d), K=512(r), split-R(4). 64x32 tile, 4x2x2 micro.
// grid (16, 4, 4) = 256 blocks, 256 threads, whole tile in smem.
// ---------------------------------------------------------------------------
#define K4_PAD 68
#define K4_SMEM_BYTES ((128 * K4_PAD + 2 * 128 * 32) * 4)   // 67584

__global__ __launch_bounds__(256, 3) void k4_gemm(const float* __restrict__ c)
{
    extern __shared__ __align__(16) float sm4[];
    float* Ac = sm4;                   // [r][m] coef
    float* Bc = Ac + 128 * K4_PAD;     // [r][n] c
    float* Bq = Bc + 128 * 32;         // [r][n] c^2

    int bm0 = blockIdx.x * 64;
    int bn0 = blockIdx.y * 32;
    int r0  = blockIdx.z * 128;
    int tid = threadIdx.x;

#pragma unroll
    for (int it = 0; it < 8; it++) {
        int i = tid + it * 256;
        int row = i >> 5, c4 = (i & 31) * 4;
        float4 a = *(const float4*)&g_coef[(bm0 + row) * NR + r0 + c4];
        Ac[(c4 + 0) * K4_PAD + row] = a.x;
        Ac[(c4 + 1) * K4_PAD + row] = a.y;
        Ac[(c4 + 2) * K4_PAD + row] = a.z;
        Ac[(c4 + 3) * K4_PAD + row] = a.w;
    }
#pragma unroll
    for (int it = 0; it < 4; it++) {
        int i = tid + it * 256;
        int row = i >> 3, c4 = (i & 7) * 4;
        float4 cc = *(const float4*)&c[(r0 + row) * ND + bn0 + c4];
        *(float4*)&Bc[row * 32 + c4] = cc;
        float4 q2 = make_float4(cc.x * cc.x, cc.y * cc.y, cc.z * cc.z, cc.w * cc.w);
        *(float4*)&Bq[row * 32 + c4] = q2;
    }
    __syncthreads();

    int tm = tid >> 4, tn = tid & 15;
    float aq[4][2] = {};
    float as_[4][2] = {};

#pragma unroll 8
    for (int kk = 0; kk < 128; kk++) {
        float4 a4 = *(const float4*)&Ac[kk * K4_PAD + tm * 4];
        float2 bc = *(const float2*)&Bc[kk * 32 + tn * 2];
        float2 bq = *(const float2*)&Bq[kk * 32 + tn * 2];
        float ai[4] = {a4.x, a4.y, a4.z, a4.w};
#pragma unroll
        for (int i = 0; i < 4; i++) {
            aq[i][0] = fmaf(ai[i], bc.x, aq[i][0]);
            aq[i][1] = fmaf(ai[i], bc.y, aq[i][1]);
            as_[i][0] = fmaf(ai[i], bq.x, as_[i][0]);
            as_[i][1] = fmaf(ai[i], bq.y, as_[i][1]);
        }
    }

    float* Qp = g_Qp + (size_t)blockIdx.z * NB * ND;
    float* Sp = g_Sp + (size_t)blockIdx.z * NB * ND;
#pragma unroll
    for (int i = 0; i < 4; i++) {
        int b = bm0 + tm * 4 + i;
        int k = bn0 + tn * 2;
        *(float2*)&Qp[b * ND + k] = make_float2(aq[i][0], aq[i][1]);
        *(float2*)&Sp[b * ND + k] = make_float2(as_[i][0], as_[i][1]);
    }
}

// ---------------------------------------------------------------------------
// K5: merge partials + new_attn = max(attn - lam_a*(z^2*P - 2z*Q + S), 0)
// ---------------------------------------------------------------------------
__global__ __launch_bounds__(256) void k5_attn(
    const float* __restrict__ z, const float* __restrict__ attn,
    float* __restrict__ out_attn)
{
    int idx = blockIdx.x * 256 + threadIdx.x;
    int b = idx >> 7;
    float Q = g_Qp[idx] + g_Qp[NB * ND + idx]
            + g_Qp[2 * NB * ND + idx] + g_Qp[3 * NB * ND + idx];
    float S = g_Sp[idx] + g_Sp[NB * ND + idx]
            + g_Sp[2 * NB * ND + idx] + g_Sp[3 * NB * ND + idx];
    float zz = z[idx];
    float P = g_P[b];
    float grad = fmaf(zz * zz, P, fmaf(-2.f * zz, Q, S));
    out_attn[idx] = fmaxf(fmaf(-LAM_A, grad, attn[idx]), 0.f);
}

// ---------------------------------------------------------------------------
extern "C" void kernel_launch(void* const* d_in, const int* in_sizes, int n_in,
                              void* d_out, int out_size)
{
    const float* z     = (const float*)d_in[0];  // (B,D)
    const float* label = (const float*)d_in[1];  // (B,O)
    const float* attn  = (const float*)d_in[2];  // (B,D)
    const float* assoc = (const float*)d_in[3];  // (B,R,O)
    const float* c     = (const float*)d_in[4];  // (R,D)

    float* out       = (float*)d_out;
    float* out_x     = out;                       // (B,O)
    float* out_attn  = out + NB * NO;             // (B,D)
    float* out_assoc = out + NB * NO + NB * ND;   // (B,R,O)

    static bool attr_done = false;
    if (!attr_done) {
        cudaFuncSetAttribute(k4_gemm, cudaFuncAttributeMaxDynamicSharedMemorySize,
                             K4_SMEM_BYTES);
        attr_done = true;
    }

    k0_transpose<<<dim3(NR / 32, ND / 32), 256>>>(c);
    k23<<<NB, 512>>>(assoc, label, z, attn, out_x, out_assoc);
    k4_gemm<<<dim3(NB / 64, ND / 32, 4), 256, K4_SMEM_BYTES>>>(c);
    k5_attn<<<NB * ND / 256, 256>>>(z, attn, out_attn);
}

// round 15
// speedup vs baseline: 1.7181x; 1.7181x over previous
#include <cuda_runtime.h>

#define NB 1024
#define NR 512
#define ND 128
#define NO 64
#define BETA 6.5f
#define LAM_A 0.0033f
#define LAM_W 0.003f

// scratch (allocation-free rule: __device__ globals)
__device__ float g_qp[2 * NB * NR];     // k1 split-D partials
__device__ float g_coef[NB * NR];
__device__ float g_P[NB];
__device__ float g_Qp[4 * NB * ND];     // k4 split-R partials
__device__ float g_Sp[4 * NB * ND];

// ---------------------------------------------------------------------------
// K1: partial q[b,r] = sum_{d in half} (-2az)*c + a*c^2
// 64x64 tile, split-D(2), whole tile resident in smem.
// grid (16, 8, 2) = 256 blocks, 256 threads, 3 CTAs/SM.
// ---------------------------------------------------------------------------
#define K1_PAD 68
#define K1_SMEM_BYTES (4 * 64 * K1_PAD * 4)   // 69632

__global__ __launch_bounds__(256, 3) void k1_gemm(
    const float* __restrict__ z, const float* __restrict__ attn,
    const float* __restrict__ c)
{
    extern __shared__ __align__(16) float sm[];
    float* Au = sm;                    // [d][m] -2*a*z
    float* Av = Au + 64 * K1_PAD;      // [d][m] a
    float* Bc = Av + 64 * K1_PAD;      // [d][n] c
    float* Bq = Bc + 64 * K1_PAD;      // [d][n] c^2

    int bm0 = blockIdx.x * 64;
    int bn0 = blockIdx.y * 64;
    int d0  = blockIdx.z * 64;
    int tid = threadIdx.x;

#pragma unroll
    for (int it = 0; it < 4; it++) {
        int i = tid + it * 256;
        int row = i >> 4, c4 = (i & 15) * 4;
        float4 a  = *(const float4*)&attn[(bm0 + row) * ND + d0 + c4];
        float4 zz = *(const float4*)&z[(bm0 + row) * ND + d0 + c4];
        Au[(c4 + 0) * K1_PAD + row] = -2.f * a.x * zz.x;
        Au[(c4 + 1) * K1_PAD + row] = -2.f * a.y * zz.y;
        Au[(c4 + 2) * K1_PAD + row] = -2.f * a.z * zz.z;
        Au[(c4 + 3) * K1_PAD + row] = -2.f * a.w * zz.w;
        Av[(c4 + 0) * K1_PAD + row] = a.x;
        Av[(c4 + 1) * K1_PAD + row] = a.y;
        Av[(c4 + 2) * K1_PAD + row] = a.z;
        Av[(c4 + 3) * K1_PAD + row] = a.w;
        float4 cc = *(const float4*)&c[(bn0 + row) * ND + d0 + c4];
        Bc[(c4 + 0) * K1_PAD + row] = cc.x;
        Bc[(c4 + 1) * K1_PAD + row] = cc.y;
        Bc[(c4 + 2) * K1_PAD + row] = cc.z;
        Bc[(c4 + 3) * K1_PAD + row] = cc.w;
        Bq[(c4 + 0) * K1_PAD + row] = cc.x * cc.x;
        Bq[(c4 + 1) * K1_PAD + row] = cc.y * cc.y;
        Bq[(c4 + 2) * K1_PAD + row] = cc.z * cc.z;
        Bq[(c4 + 3) * K1_PAD + row] = cc.w * cc.w;
    }
    __syncthreads();

    int tm = tid >> 4, tn = tid & 15;
    float acc[4][4] = {};

#pragma unroll 8
    for (int kk = 0; kk < 64; kk++) {
        float4 u = *(const float4*)&Au[kk * K1_PAD + tm * 4];
        float4 v = *(const float4*)&Av[kk * K1_PAD + tm * 4];
        float4 bc = *(const float4*)&Bc[kk * K1_PAD + tn * 4];
        float4 bq = *(const float4*)&Bq[kk * K1_PAD + tn * 4];
        float ui[4] = {u.x, u.y, u.z, u.w};
        float vi[4] = {v.x, v.y, v.z, v.w};
        float cj[4] = {bc.x, bc.y, bc.z, bc.w};
        float qj[4] = {bq.x, bq.y, bq.z, bq.w};
#pragma unroll
        for (int i = 0; i < 4; i++)
#pragma unroll
            for (int j = 0; j < 4; j++)
                acc[i][j] = fmaf(ui[i], cj[j], fmaf(vi[i], qj[j], acc[i][j]));
    }

    float* qp = g_qp + (size_t)blockIdx.z * NB * NR;
#pragma unroll
    for (int i = 0; i < 4; i++) {
        float4 o = make_float4(acc[i][0], acc[i][1], acc[i][2], acc[i][3]);
        *(float4*)&qp[(bm0 + tm * 4 + i) * NR + bn0 + tn * 4] = o;
    }
}

// ---------------------------------------------------------------------------
// K23: one block per b, assoc row register-resident (read DRAM exactly once,
// streaming hints so the 268MB doesn't thrash L2).
// Prologue: t0 (warp 0) -> s,h from qp partials.
// Phase 1: x[o] = sum_r s*assoc  (from registers)
// Phase A: coef[r] = h*dot(gx,assoc); new_assoc = assoc - lam_w*s*gx (regs)
// ---------------------------------------------------------------------------
__global__ __launch_bounds__(512) void k23(
    const float* __restrict__ assoc, const float* __restrict__ label,
    const float* __restrict__ z, const float* __restrict__ attn,
    float* __restrict__ out_x, float* __restrict__ out_assoc)
{
    __shared__ float ss[NR];
    __shared__ float hh[NR];
    __shared__ __align__(16) float red[32][NO];
    __shared__ __align__(16) float gx[NO];
    __shared__ __align__(16) float coef[NR];
    __shared__ float t0sh;

    int b = blockIdx.x;
    int tid = threadIdx.x;
    int o4 = tid & 15, rg = tid >> 4;

    const float4* ab4 = (const float4*)(assoc + (size_t)b * NR * NO);

    // Issue all 16 payload loads up-front (independent -> MLP 16/thread).
    // __ldcs: evict-first, single-use stream.
    float4 av[16];
#pragma unroll
    for (int i = 0; i < 16; i++)
        av[i] = __ldcs(ab4 + (rg + 32 * i) * 16 + o4);

    // t0[b] = sum_d attn*z^2  (warp 0, hidden under payload load latency)
    if (tid < 32) {
        float4 zz = *(const float4*)&z[b * ND + tid * 4];
        float4 aa = *(const float4*)&attn[b * ND + tid * 4];
        float t = aa.x * zz.x * zz.x + aa.y * zz.y * zz.y
                + aa.z * zz.z * zz.z + aa.w * zz.w * zz.w;
#pragma unroll
        for (int off = 16; off; off >>= 1)
            t += __shfl_xor_sync(0xffffffffu, t, off);
        if (tid == 0) t0sh = t;
    }
    __syncthreads();

    // s,h from qp partials
    {
        float q = g_qp[b * NR + tid] + g_qp[NB * NR + b * NR + tid] + t0sh;
        q = fmaxf(q, 1e-12f);
        float dd = sqrtf(q);
        float s = __expf(-BETA * dd);
        ss[tid] = s;
        hh[tid] = -0.5f * BETA * s / dd;
    }
    __syncthreads();

    // Phase 1: x reduction from registers
    {
        float4 acc = make_float4(0.f, 0.f, 0.f, 0.f);
#pragma unroll
        for (int i = 0; i < 16; i++) {
            float s = ss[rg + 32 * i];
            acc.x = fmaf(s, av[i].x, acc.x);
            acc.y = fmaf(s, av[i].y, acc.y);
            acc.z = fmaf(s, av[i].z, acc.z);
            acc.w = fmaf(s, av[i].w, acc.w);
        }
        *(float4*)&red[rg][o4 * 4] = acc;
    }
    __syncthreads();
    if (tid < NO) {
        float x = 0.f;
#pragma unroll
        for (int g2 = 0; g2 < 32; g2++) x += red[g2][tid];
        float l = label[b * NO + tid];
        float tmin = fminf(-1.f, x);
        float teacher = tmin - l * tmin + l * fmaxf(1.f, x);
        out_x[b * NO + tid] = 2.f * x;                 // PHI = 2
        gx[tid] = 0.03125f * (x - teacher);            // (2/O)*(x - teacher)
    }
    __syncthreads();

    // Phase A: coef + new_assoc from registers (zero re-read)
    {
        float4 g4 = *(const float4*)&gx[o4 * 4];
        float4* ob4 = (float4*)(out_assoc + (size_t)b * NR * NO);
#pragma unroll
        for (int i = 0; i < 16; i++) {
            int r = rg + 32 * i;
            float p = av[i].x * g4.x + av[i].y * g4.y
                    + av[i].z * g4.z + av[i].w * g4.w;
            float f = LAM_W * ss[r];
            float4 o;
            o.x = fmaf(-f, g4.x, av[i].x);
            o.y = fmaf(-f, g4.y, av[i].y);
            o.z = fmaf(-f, g4.z, av[i].z);
            o.w = fmaf(-f, g4.w, av[i].w);
            __stcs(ob4 + r * 16 + o4, o);   // streaming store
            p += __shfl_xor_sync(0xffffffffu, p, 1);
            p += __shfl_xor_sync(0xffffffffu, p, 2);
            p += __shfl_xor_sync(0xffffffffu, p, 4);
            p += __shfl_xor_sync(0xffffffffu, p, 8);
            if (o4 == 0) coef[r] = hh[r] * p;
        }
    }
    __syncthreads();

    if (tid < NR / 4)
        ((float4*)&g_coef[b * NR])[tid] = ((const float4*)coef)[tid];
    if (tid < 32) {
        float p = 0.f;
#pragma unroll
        for (int i = 0; i < 16; i++) p += coef[tid + 32 * i];
#pragma unroll
        for (int off = 16; off; off >>= 1)
            p += __shfl_xor_sync(0xffffffffu, p, off);
        if (tid == 0) g_P[b] = p;
    }
}

// ---------------------------------------------------------------------------
// K4: dual GEMM partials  Q = coef @ C, S = coef @ C^2
// M=1024(b), N=128(d), K=512(r), split-R(4). 64x32 tile, 4x2x2 micro.
// grid (16, 4, 4) = 256 blocks, 256 threads, whole tile in smem.
// ---------------------------------------------------------------------------
#define K4_PAD 68
#define K4_SMEM_BYTES ((128 * K4_PAD + 2 * 128 * 32) * 4)   // 67584

__global__ __launch_bounds__(256, 3) void k4_gemm(const float* __restrict__ c)
{
    extern __shared__ __align__(16) float sm4[];
    float* Ac = sm4;                   // [r][m] coef
    float* Bc = Ac + 128 * K4_PAD;     // [r][n] c
    float* Bq = Bc + 128 * 32;         // [r][n] c^2

    int bm0 = blockIdx.x * 64;
    int bn0 = blockIdx.y * 32;
    int r0  = blockIdx.z * 128;
    int tid = threadIdx.x;

#pragma unroll
    for (int it = 0; it < 8; it++) {
        int i = tid + it * 256;
        int row = i >> 5, c4 = (i & 31) * 4;
        float4 a = *(const float4*)&g_coef[(bm0 + row) * NR + r0 + c4];
        Ac[(c4 + 0) * K4_PAD + row] = a.x;
        Ac[(c4 + 1) * K4_PAD + row] = a.y;
        Ac[(c4 + 2) * K4_PAD + row] = a.z;
        Ac[(c4 + 3) * K4_PAD + row] = a.w;
    }
#pragma unroll
    for (int it = 0; it < 4; it++) {
        int i = tid + it * 256;
        int row = i >> 3, c4 = (i & 7) * 4;
        float4 cc = *(const float4*)&c[(r0 + row) * ND + bn0 + c4];
        *(float4*)&Bc[row * 32 + c4] = cc;
        float4 q2 = make_float4(cc.x * cc.x, cc.y * cc.y, cc.z * cc.z, cc.w * cc.w);
        *(float4*)&Bq[row * 32 + c4] = q2;
    }
    __syncthreads();

    int tm = tid >> 4, tn = tid & 15;
    float aq[4][2] = {};
    float as_[4][2] = {};

#pragma unroll 8
    for (int kk = 0; kk < 128; kk++) {
        float4 a4 = *(const float4*)&Ac[kk * K4_PAD + tm * 4];
        float2 bc = *(const float2*)&Bc[kk * 32 + tn * 2];
        float2 bq = *(const float2*)&Bq[kk * 32 + tn * 2];
        float ai[4] = {a4.x, a4.y, a4.z, a4.w};
#pragma unroll
        for (int i = 0; i < 4; i++) {
            aq[i][0] = fmaf(ai[i], bc.x, aq[i][0]);
            aq[i][1] = fmaf(ai[i], bc.y, aq[i][1]);
            as_[i][0] = fmaf(ai[i], bq.x, as_[i][0]);
            as_[i][1] = fmaf(ai[i], bq.y, as_[i][1]);
        }
    }

    float* Qp = g_Qp + (size_t)blockIdx.z * NB * ND;
    float* Sp = g_Sp + (size_t)blockIdx.z * NB * ND;
#pragma unroll
    for (int i = 0; i < 4; i++) {
        int b = bm0 + tm * 4 + i;
        int k = bn0 + tn * 2;
        *(float2*)&Qp[b * ND + k] = make_float2(aq[i][0], aq[i][1]);
        *(float2*)&Sp[b * ND + k] = make_float2(as_[i][0], as_[i][1]);
    }
}

// ---------------------------------------------------------------------------
// K5: merge partials + attention update, float4-vectorized.
// Each thread handles 4 contiguous elements: 10 independent float4 loads.
// grid = NB*ND/(256*4) = 128 blocks.
// ---------------------------------------------------------------------------
__global__ __launch_bounds__(256) void k5_attn(
    const float* __restrict__ z, const float* __restrict__ attn,
    float* __restrict__ out_attn)
{
    int i4 = blockIdx.x * 256 + threadIdx.x;     // float4 index
    int b = (i4 * 4) >> 7;                       // 32 float4 per b-row
    const float4* Qp = (const float4*)g_Qp;
    const float4* Sp = (const float4*)g_Sp;
    const int STRIDE4 = NB * ND / 4;

    float4 q0 = Qp[i4], q1 = Qp[STRIDE4 + i4];
    float4 q2 = Qp[2 * STRIDE4 + i4], q3 = Qp[3 * STRIDE4 + i4];
    float4 s0 = Sp[i4], s1 = Sp[STRIDE4 + i4];
    float4 s2 = Sp[2 * STRIDE4 + i4], s3 = Sp[3 * STRIDE4 + i4];
    float4 zz = ((const float4*)z)[i4];
    float4 aa = ((const float4*)attn)[i4];
    float P = g_P[b];

    float4 Q, S, o;
    Q.x = q0.x + q1.x + q2.x + q3.x;  S.x = s0.x + s1.x + s2.x + s3.x;
    Q.y = q0.y + q1.y + q2.y + q3.y;  S.y = s0.y + s1.y + s2.y + s3.y;
    Q.z = q0.z + q1.z + q2.z + q3.z;  S.z = s0.z + s1.z + s2.z + s3.z;
    Q.w = q0.w + q1.w + q2.w + q3.w;  S.w = s0.w + s1.w + s2.w + s3.w;

    o.x = fmaxf(fmaf(-LAM_A, fmaf(zz.x * zz.x, P, fmaf(-2.f * zz.x, Q.x, S.x)), aa.x), 0.f);
    o.y = fmaxf(fmaf(-LAM_A, fmaf(zz.y * zz.y, P, fmaf(-2.f * zz.y, Q.y, S.y)), aa.y), 0.f);
    o.z = fmaxf(fmaf(-LAM_A, fmaf(zz.z * zz.z, P, fmaf(-2.f * zz.z, Q.z, S.z)), aa.z), 0.f);
    o.w = fmaxf(fmaf(-LAM_A, fmaf(zz.w * zz.w, P, fmaf(-2.f * zz.w, Q.w, S.w)), aa.w), 0.f);

    ((float4*)out_attn)[i4] = o;
}

// ---------------------------------------------------------------------------
extern "C" void kernel_launch(void* const* d_in, const int* in_sizes, int n_in,
                              void* d_out, int out_size)
{
    const float* z     = (const float*)d_in[0];  // (B,D)
    const float* label = (const float*)d_in[1];  // (B,O)
    const float* attn  = (const float*)d_in[2];  // (B,D)
    const float* assoc = (const float*)d_in[3];  // (B,R,O)
    const float* c     = (const float*)d_in[4];  // (R,D)

    float* out       = (float*)d_out;
    float* out_x     = out;                       // (B,O)
    float* out_attn  = out + NB * NO;             // (B,D)
    float* out_assoc = out + NB * NO + NB * ND;   // (B,R,O)

    static bool attr_done = false;
    if (!attr_done) {
        cudaFuncSetAttribute(k1_gemm, cudaFuncAttributeMaxDynamicSharedMemorySize,
                             K1_SMEM_BYTES);
        cudaFuncSetAttribute(k4_gemm, cudaFuncAttributeMaxDynamicSharedMemorySize,
                             K4_SMEM_BYTES);
        attr_done = true;
    }

    k1_gemm<<<dim3(NB / 64, NR / 64, 2), 256, K1_SMEM_BYTES>>>(z, attn, c);
    k23<<<NB, 512>>>(assoc, label, z, attn, out_x, out_assoc);
    k4_gemm<<<dim3(NB / 64, ND / 32, 4), 256, K4_SMEM_BYTES>>>(c);
    k5_attn<<<NB * ND / 1024, 256>>>(z, attn, out_attn);
}